// round 14
// baseline (speedup 1.0000x reference)
#include <cuda_runtime.h>
#include <cuda_bf16.h>
#include <math.h>
#include <stdint.h>

#define BB 16
#define CQ 256
#define CK 2048
#define NN 4096
#define NCLS 40

// ---- scratch (static __device__ arrays; no allocation) ----
__device__ __nv_bfloat16 g_imgh[(size_t)BB * NN * CQ];
__device__ __nv_bfloat16 g_pch[(size_t)BB * NN * CK];
__device__ __nv_bfloat16 g_wqh[CQ * CQ];
__device__ __nv_bfloat16 g_wkh[CQ * CK];
__device__ __nv_bfloat16 g_qh[(size_t)BB * NN * CQ];
__device__ __nv_bfloat16 g_kh[(size_t)BB * NN * CQ];
__device__ __nv_bfloat16 g_Sh[(size_t)BB * NN * NN];   // column-permuted per 64-block
__device__ float g_rowmax[BB * NN];
__device__ float g_rowsum[BB * NN];
__device__ float g_wpart[32 * BB * NN];
__device__ float g_w[BB * NN];
__device__ float g_ximg[BB * CQ];
__device__ float g_imgmean[BB * CQ];
__device__ float g_xpc[BB * CK];
__device__ float g_fused[BB * (CQ + CK)];

// ============================================================
// helpers
// ============================================================
__device__ __forceinline__ uint32_t smem_u32(const void* p) {
    uint32_t a;
    asm("{ .reg .u64 t; cvta.to.shared.u64 t, %1; cvt.u32.u64 %0, t; }" : "=r"(a) : "l"(p));
    return a;
}
__device__ __forceinline__ uint32_t packbf(float x, float y) {
    __nv_bfloat162 h = __floats2bfloat162_rn(x, y);
    return *reinterpret_cast<uint32_t*>(&h);
}
__device__ __forceinline__ void mma_bf16(float* c, const uint32_t* a, uint32_t b0, uint32_t b1)
{
    asm volatile(
        "mma.sync.aligned.m16n8k16.row.col.f32.bf16.bf16.f32 "
        "{%0,%1,%2,%3},{%4,%5,%6,%7},{%8,%9},{%0,%1,%2,%3};"
        : "+f"(c[0]), "+f"(c[1]), "+f"(c[2]), "+f"(c[3])
        : "r"(a[0]), "r"(a[1]), "r"(a[2]), "r"(a[3]), "r"(b0), "r"(b1));
}
__device__ __forceinline__ void ldm_x4(uint32_t* r, uint32_t addr)
{
    asm volatile("ldmatrix.sync.aligned.m8n8.x4.shared.b16 {%0,%1,%2,%3}, [%4];"
        : "=r"(r[0]), "=r"(r[1]), "=r"(r[2]), "=r"(r[3]) : "r"(addr));
}
#define CP_A16(dst, src) \
    asm volatile("cp.async.ca.shared.global [%0], [%1], 16;" :: "r"(dst), "l"(src))
#define CP_COMMIT() asm volatile("cp.async.commit_group;" ::: "memory")
#define CP_WAIT1()  asm volatile("cp.async.wait_group 1;" ::: "memory")
#define CP_WAIT0()  asm volatile("cp.async.wait_group 0;" ::: "memory")

// ============================================================
// Transpose-convert tile: 64 c-rows x 32 n-cols -> [n][c] bf16.
// ============================================================
__device__ __forceinline__ void cvt_tile64(const float* __restrict__ ib,
                                           __nv_bfloat16* __restrict__ ob, int C)
{
    __shared__ float sm[64][33];
    const int lane = threadIdx.x & 31, warp = threadIdx.x >> 5;

    #pragma unroll
    for (int i = 0; i < 8; i++) {
        int c = warp * 8 + i;
        sm[c][lane] = ib[(size_t)c * NN + lane];
    }
    __syncthreads();
    #pragma unroll
    for (int j = 0; j < 4; j++) {
        int n = warp * 4 + j;
        *reinterpret_cast<__nv_bfloat162*>(ob + (size_t)n * C + lane * 2) =
            __floats2bfloat162_rn(sm[lane * 2][n], sm[lane * 2 + 1][n]);
    }
}

__global__ __launch_bounds__(256) void cvt_imgw_kernel(const float* __restrict__ img,
                                                       const float* __restrict__ Wq,
                                                       const float* __restrict__ Wk)
{
    const int y = blockIdx.y;
    if (y < 4) {
        const int b = blockIdx.z, c0 = y * 64, n0 = blockIdx.x * 32;
        cvt_tile64(img + ((size_t)b * CQ + c0) * NN + n0,
                   g_imgh + ((size_t)b * NN + n0) * CQ + c0, CQ);
    } else {
        const int tid = threadIdx.x;
        const int total = CQ * CQ + CQ * CK;
        int i = (blockIdx.z * 128 + blockIdx.x) * 256 + tid;
        for (; i < total; i += 128 * 16 * 256) {
            if (i < CQ * CQ) g_wqh[i] = __float2bfloat16_rn(Wq[i]);
            else             g_wkh[i - CQ * CQ] = __float2bfloat16_rn(Wk[i - CQ * CQ]);
        }
    }
}

template <int HALF>
__global__ __launch_bounds__(256) void cvt_pc_half(const float* __restrict__ pc2d)
{
    const int b = blockIdx.z;
    const int c0 = (HALF * 16 + blockIdx.y) * 64;
    const int n0 = blockIdx.x * 32;
    cvt_tile64(pc2d + ((size_t)b * CK + c0) * NN + n0,
               g_pch + ((size_t)b * NN + n0) * CK + c0, CK);
}

// ============================================================
// Projection GEMM — R8-measured structure.
// ============================================================
#define PJ_PITCH 68
#define PJ_TSZ   (128 * PJ_PITCH)
#define PROJ_SMEM (4 * PJ_TSZ * 4)

template <int KDIM, int WHICH>
__global__ __launch_bounds__(512) void proj_kernel(const __nv_bfloat16* __restrict__ Wh,
                                                   const __nv_bfloat16* __restrict__ Xh,
                                                   const float* __restrict__ bias)
{
    extern __shared__ uint32_t smu[];
    const int b  = blockIdx.z;
    const int m0 = blockIdx.y * 128;
    const int n0 = blockIdx.x * 128;
    const int tid = threadIdx.x;
    const int lane = tid & 31, w = tid >> 5;
    const int wq = w & 7, wh = w >> 3;
    const int gid = lane >> 2, tig = lane & 3;
    const int NCH = KDIM / 128;
    const __nv_bfloat16* Xb = Xh + (size_t)b * NN * KDIM + (size_t)n0 * KDIM;

    const uint32_t sbase = smem_u32(smu);
    const uint32_t aoff = ((wq * 16 + (lane & 15)) * PJ_PITCH + ((lane & 16) ? 4 : 0)) * 4;
    const uint32_t boff = ((wh * 64 + (lane & 7) + ((lane & 16) >> 1)) * PJ_PITCH + ((lane & 8) ? 4 : 0)) * 4;

    float acc[8][4];
    #pragma unroll
    for (int t = 0; t < 8; t++)
        #pragma unroll
        for (int j = 0; j < 4; j++) acc[t][j] = 0.f;

    #pragma unroll
    for (int l = 0; l < 4; l++) {
        int i = tid + l * 512;
        int r = i >> 4, c = i & 15;
        CP_A16(smem_u32(smu + r * PJ_PITCH + c * 4), Wh + (size_t)(m0 + r) * KDIM + c * 8);
    }
    #pragma unroll
    for (int l = 0; l < 4; l++) {
        int i = tid + l * 512;
        int r = i >> 4, c = i & 15;
        CP_A16(smem_u32(smu + 2 * PJ_TSZ + r * PJ_PITCH + c * 4), Xb + (size_t)r * KDIM + c * 8);
    }
    CP_COMMIT();
    CP_WAIT0();
    __syncthreads();

    for (int kc = 0; kc < NCH; kc++) {
        const int cur = kc & 1, nxt = cur ^ 1;
        if (kc + 1 < NCH) {
            const int kb = (kc + 1) * 128;
            #pragma unroll
            for (int l = 0; l < 4; l++) {
                int i = tid + l * 512;
                int r = i >> 4, c = i & 15;
                CP_A16(smem_u32(smu + nxt * PJ_TSZ + r * PJ_PITCH + c * 4),
                       Wh + (size_t)(m0 + r) * KDIM + kb + c * 8);
            }
            #pragma unroll
            for (int l = 0; l < 4; l++) {
                int i = tid + l * 512;
                int r = i >> 4, c = i & 15;
                CP_A16(smem_u32(smu + (2 + nxt) * PJ_TSZ + r * PJ_PITCH + c * 4),
                       Xb + (size_t)r * KDIM + kb + c * 8);
            }
        }
        CP_COMMIT();

        const uint32_t abase = sbase + (uint32_t)(cur * PJ_TSZ) * 4 + aoff;
        const uint32_t bbase = sbase + (uint32_t)((2 + cur) * PJ_TSZ) * 4 + boff;
        #pragma unroll
        for (int ks = 0; ks < 8; ks++) {
            uint32_t a[4];
            ldm_x4(a, abase + ks * 32);
            #pragma unroll
            for (int j = 0; j < 4; j++) {
                uint32_t bf[4];
                ldm_x4(bf, bbase + (uint32_t)(j * 16 * PJ_PITCH) * 4 + ks * 32);
                mma_bf16(acc[2 * j],     a, bf[0], bf[1]);
                mma_bf16(acc[2 * j + 1], a, bf[2], bf[3]);
            }
        }
        CP_WAIT0();
        __syncthreads();
    }

    __nv_bfloat16* out = (WHICH == 0) ? g_qh : g_kh;
    const int R0 = m0 + wq * 16 + gid;
    const float bv0 = bias[R0], bv1 = bias[R0 + 8];
    #pragma unroll
    for (int t = 0; t < 8; t++) {
        int n = n0 + wh * 64 + t * 8 + tig * 2;
        __nv_bfloat16* p0 = out + ((size_t)b * NN + n) * CQ;
        __nv_bfloat16* p1 = p0 + CQ;
        p0[R0]     = __float2bfloat16_rn(acc[t][0] + bv0);
        p1[R0]     = __float2bfloat16_rn(acc[t][1] + bv0);
        p0[R0 + 8] = __float2bfloat16_rn(acc[t][2] + bv1);
        p1[R0 + 8] = __float2bfloat16_rn(acc[t][3] + bv1);
    }
}

// ============================================================
// Attention pass 1 — R11-measured (526us): fused online stats.
// ============================================================
#define P1_PITCH 132
#define P1_A (256 * P1_PITCH)
#define P1_B (128 * PJ_PITCH)
#define P1_SMEM ((P1_A + 2 * P1_B + 1024) * 4)

__global__ __launch_bounds__(512) void attn_pass1()
{
    extern __shared__ uint32_t smu[];
    float* smM = reinterpret_cast<float*>(smu + P1_A + 2 * P1_B);   // [2][256]
    float* smS = smM + 512;

    const int b  = blockIdx.y;
    const int m0 = blockIdx.x * 256;
    const int tid = threadIdx.x;
    const int lane = tid & 31, w = tid >> 5;
    const int wq = w & 7, wh = w >> 3;
    const int gid = lane >> 2, tig = lane & 3;

    const uint32_t sbase = smem_u32(smu);
    const uint32_t aoff = ((wq * 32 + (lane & 15)) * P1_PITCH + ((lane & 16) ? 4 : 0)) * 4;
    const uint32_t boff = ((wh * 64 + (lane & 7) + ((lane & 16) >> 1)) * PJ_PITCH + ((lane & 8) ? 4 : 0)) * 4;

    auto load_stage = [&](int st) {
        const int s = st >> 1, kc = st & 1;
        const __nv_bfloat16* src = g_kh + ((size_t)b * NN + s * 128) * CQ + kc * 128;
        #pragma unroll
        for (int l = 0; l < 4; l++) {
            int i = tid + l * 512;
            int r = i >> 4, c = i & 15;
            CP_A16(smem_u32(smu + P1_A + (st & 1) * P1_B + r * PJ_PITCH + c * 4),
                   src + (size_t)r * CQ + c * 8);
        }
    };

    {
        #pragma unroll
        for (int l = 0; l < 16; l++) {
            int i = tid + l * 512;
            int r = i >> 5, c = i & 31;
            CP_A16(smem_u32(smu + r * P1_PITCH + c * 4),
                   g_qh + ((size_t)b * NN + m0 + r) * CQ + c * 8);
        }
        load_stage(0);
        CP_COMMIT();
        load_stage(1);
        CP_COMMIT();
    }

    float acc[2][8][4];
    #pragma unroll
    for (int mi = 0; mi < 2; mi++)
        #pragma unroll
        for (int t = 0; t < 8; t++)
            #pragma unroll
            for (int j = 0; j < 4; j++) acc[mi][t][j] = 0.f;

    float run_m[4], run_s[4];
    #pragma unroll
    for (int k = 0; k < 4; k++) { run_m[k] = -INFINITY; run_s[k] = 0.f; }

    for (int st = 0; st < 64; st++) {
        CP_WAIT1();
        __syncthreads();

        const int kc = st & 1;
        const uint32_t bbase = sbase + (uint32_t)(P1_A + (st & 1) * P1_B) * 4;
        #pragma unroll
        for (int ks = 0; ks < 8; ks++) {
            uint32_t a0[4], a1[4];
            ldm_x4(a0, sbase + aoff + (kc * 8 + ks) * 32);
            ldm_x4(a1, sbase + aoff + 16 * P1_PITCH * 4 + (kc * 8 + ks) * 32);
            #pragma unroll
            for (int nt = 0; nt < 4; nt++) {
                uint32_t bf[4];
                ldm_x4(bf, bbase + boff + (uint32_t)(nt * 16 * PJ_PITCH) * 4 + ks * 32);
                mma_bf16(acc[0][nt * 2],     a0, bf[0], bf[1]);
                mma_bf16(acc[0][nt * 2 + 1], a0, bf[2], bf[3]);
                mma_bf16(acc[1][nt * 2],     a1, bf[0], bf[1]);
                mma_bf16(acc[1][nt * 2 + 1], a1, bf[2], bf[3]);
            }
        }
        __syncthreads();

        if (st + 2 < 64) load_stage(st + 2);
        CP_COMMIT();

        if (st & 1) {
            const int s = st >> 1;
            #pragma unroll
            for (int mi = 0; mi < 2; mi++) {
                #pragma unroll
                for (int rr = 0; rr < 2; rr++) {
                    const int k = mi * 2 + rr;
                    float vm = -INFINITY;
                    #pragma unroll
                    for (int t = 0; t < 8; t++)
                        vm = fmaxf(vm, fmaxf(acc[mi][t][rr * 2], acc[mi][t][rr * 2 + 1]));
                    vm = fmaxf(vm, __shfl_xor_sync(0xffffffffu, vm, 1));
                    vm = fmaxf(vm, __shfl_xor_sync(0xffffffffu, vm, 2));
                    const float nm = fmaxf(run_m[k], vm);
                    float ss = 0.f;
                    #pragma unroll
                    for (int t = 0; t < 8; t++)
                        ss += __expf(acc[mi][t][rr * 2] - nm) + __expf(acc[mi][t][rr * 2 + 1] - nm);
                    ss += __shfl_xor_sync(0xffffffffu, ss, 1);
                    ss += __shfl_xor_sync(0xffffffffu, ss, 2);
                    run_s[k] = run_s[k] * __expf(run_m[k] - nm) + ss;
                    run_m[k] = nm;

                    const int row = m0 + wq * 32 + mi * 16 + gid + rr * 8;
                    uint32_t pk[8];
                    #pragma unroll
                    for (int t = 0; t < 8; t++)
                        pk[t] = packbf(acc[mi][t][rr * 2], acc[mi][t][rr * 2 + 1]);
                    __nv_bfloat16* dst = g_Sh + ((size_t)b * NN + row) * NN + s * 128 + wh * 64 + tig * 16;
                    *reinterpret_cast<uint4*>(dst)     = *reinterpret_cast<uint4*>(pk);
                    *reinterpret_cast<uint4*>(dst + 8) = *reinterpret_cast<uint4*>(pk + 4);
                }
            }
            #pragma unroll
            for (int mi = 0; mi < 2; mi++)
                #pragma unroll
                for (int t = 0; t < 8; t++)
                    #pragma unroll
                    for (int j = 0; j < 4; j++) acc[mi][t][j] = 0.f;
        }
    }

    if (tig == 0) {
        #pragma unroll
        for (int k = 0; k < 4; k++) {
            const int r = wq * 32 + (k >> 1) * 16 + gid + (k & 1) * 8;
            smM[wh * 256 + r] = run_m[k];
            smS[wh * 256 + r] = run_s[k];
        }
    }
    __syncthreads();
    if (tid < 256) {
        float ma = smM[tid], mb = smM[256 + tid];
        float sa = smS[tid], sb = smS[256 + tid];
        float nm = fmaxf(ma, mb);
        g_rowmax[b * NN + m0 + tid] = nm;
        g_rowsum[b * NN + m0 + tid] = sa * __expf(ma - nm) + sb * __expf(mb - nm);
    }
}

// ============================================================
// Attention pass 2: stream bf16 S (permuted order), per-slice column sums.
// ============================================================
__global__ __launch_bounds__(256) void attn_pass2()
{
    __shared__ float rm[128], rz[128];
    const int b  = blockIdx.z;
    const int ms = blockIdx.y;
    const int nb = blockIdx.x * 2048;
    const int tid = threadIdx.x;

    if (tid < 128) {
        rm[tid] = g_rowmax[b * NN + ms * 128 + tid];
        rz[tid] = 1.0f / g_rowsum[b * NN + ms * 128 + tid];
    }
    __syncthreads();

    const __nv_bfloat16* Sp = g_Sh + ((size_t)b * NN + ms * 128) * NN + nb + tid * 8;
    float a[8];
    #pragma unroll
    for (int i = 0; i < 8; i++) a[i] = 0.f;

    for (int m = 0; m < 128; m++) {
        uint4 r = *reinterpret_cast<const uint4*>(Sp + (size_t)m * NN);
        float mx = rm[m], z = rz[m];
        __nv_bfloat162 p0 = *reinterpret_cast<__nv_bfloat162*>(&r.x);
        __nv_bfloat162 p1 = *reinterpret_cast<__nv_bfloat162*>(&r.y);
        __nv_bfloat162 p2 = *reinterpret_cast<__nv_bfloat162*>(&r.z);
        __nv_bfloat162 p3 = *reinterpret_cast<__nv_bfloat162*>(&r.w);
        a[0] += __expf(__bfloat162float(p0.x) - mx) * z;
        a[1] += __expf(__bfloat162float(p0.y) - mx) * z;
        a[2] += __expf(__bfloat162float(p1.x) - mx) * z;
        a[3] += __expf(__bfloat162float(p1.y) - mx) * z;
        a[4] += __expf(__bfloat162float(p2.x) - mx) * z;
        a[5] += __expf(__bfloat162float(p2.y) - mx) * z;
        a[6] += __expf(__bfloat162float(p3.x) - mx) * z;
        a[7] += __expf(__bfloat162float(p3.y) - mx) * z;
    }
    const float sc = 1.0f / NN;
    float* wp = g_wpart + (size_t)ms * (BB * NN) + b * NN + nb + tid * 8;
    *reinterpret_cast<float4*>(wp)     = make_float4(a[0] * sc, a[1] * sc, a[2] * sc, a[3] * sc);
    *reinterpret_cast<float4*>(wp + 4) = make_float4(a[4] * sc, a[5] * sc, a[6] * sc, a[7] * sc);
}

// reduce + inverse column permutation
__global__ void reduce_w_kernel()
{
    const int flat = blockIdx.x * 256 + threadIdx.x;
    const int a = flat & 63;
    const int sa = ((a & 7) >> 1) * 16 + ((a >> 3) & 7) * 2 + (a & 1);
    const int src = (flat & ~63) | sa;
    float s = 0.f;
    #pragma unroll
    for (int ms = 0; ms < 32; ms++) s += g_wpart[ms * (BB * NN) + src];
    g_w[flat] = s;
}

// ============================================================
// Weighted/plain reductions — NOW FROM bf16 [n][c] COPIES (half traffic,
// fully coalesced, no cross-thread reduce until tiny end-merge).
// grid (9, BB): x=0 -> img chunk (CQ=256 ch); x=1..8 -> pc chunk of 256 ch.
// block 256: cg = tid&63 owns 4 channels (uint2 per load); ng = tid>>6 covers
// n = ng mod 4. Partials merged in smem.
// ============================================================
__global__ __launch_bounds__(256) void reduce_xw_kernel()
{
    __shared__ float ws[NN];
    __shared__ float red1[4][256];   // [ng][ch in chunk]
    __shared__ float red2[4][256];
    const int b = blockIdx.y;
    const int chunk = blockIdx.x;
    const int tid = threadIdx.x;
    const int cg = tid & 63, ng = tid >> 6;

    for (int i = tid; i < NN; i += 256) ws[i] = g_w[b * NN + i];
    __syncthreads();

    const bool isimg = (chunk == 0);
    const int C = isimg ? CQ : CK;
    const int c0 = isimg ? 0 : (chunk - 1) * 256;
    const __nv_bfloat16* X = (isimg ? g_imgh + (size_t)b * NN * CQ
                                    : g_pch + (size_t)b * NN * CK) + c0 + cg * 4;

    float s1[4] = {0.f, 0.f, 0.f, 0.f};
    float s2[4] = {0.f, 0.f, 0.f, 0.f};
    for (int n = ng; n < NN; n += 4) {
        uint2 v = *reinterpret_cast<const uint2*>(X + (size_t)n * C);
        __nv_bfloat162 p0 = *reinterpret_cast<__nv_bfloat162*>(&v.x);
        __nv_bfloat162 p1 = *reinterpret_cast<__nv_bfloat162*>(&v.y);
        const float wv = ws[n];
        float x0 = __bfloat162float(p0.x), x1 = __bfloat162float(p0.y);
        float x2 = __bfloat162float(p1.x), x3 = __bfloat162float(p1.y);
        s1[0] += wv * x0; s1[1] += wv * x1; s1[2] += wv * x2; s1[3] += wv * x3;
        s2[0] += x0; s2[1] += x1; s2[2] += x2; s2[3] += x3;
    }
    #pragma unroll
    for (int j = 0; j < 4; j++) {
        red1[ng][cg * 4 + j] = s1[j];
        red2[ng][cg * 4 + j] = s2[j];
    }
    __syncthreads();
    if (tid < 256 && ng == 0) {}  // all threads participate below
    {
        const int ch = tid;      // 0..255 channel within chunk
        if (ch < 256) {
            float a = red1[0][ch] + red1[1][ch] + red1[2][ch] + red1[3][ch];
            float m = red2[0][ch] + red2[1][ch] + red2[2][ch] + red2[3][ch];
            if (isimg) {
                g_ximg[b * CQ + ch] = a;
                g_imgmean[b * CQ + ch] = m * (1.0f / NN);
            } else {
                g_xpc[b * CK + c0 + ch] = a;
            }
        }
    }
}

// ============================================================
// Fused vector — img part
// ============================================================
__global__ void fuse_img_kernel(const float* __restrict__ Wvi, const float* __restrict__ bvi,
                                const float* __restrict__ gamma1)
{
    const int b = blockIdx.x;
    const int t = threadIdx.x;
    __shared__ float xs[CQ];
    if (t < CQ) xs[t] = g_ximg[b * CQ + t];
    __syncthreads();
    float acc = 0.f;
    const float* wr = Wvi + (size_t)t * CQ;
    for (int i = 0; i < CQ; i++) acc += wr[i] * xs[i];
    float g = gamma1[0];
    g_fused[b * (CQ + CK) + t] = g * (acc + bvi[t]) + g_imgmean[b * CQ + t];
}

// ============================================================
// Fused vector — pc part (batched coalesced GEMV)
// ============================================================
#define FP_SMEM (BB * CK * 4)

__global__ __launch_bounds__(256) void fuse_pc_kernel(const float* __restrict__ Wvp,
                                                      const float* __restrict__ bvp)
{
    extern __shared__ float xs[];
    const int tid = threadIdx.x;
    const int warp = tid >> 5, lane = tid & 31;

    for (int i = tid; i < BB * CK; i += 256) xs[i] = g_xpc[i];
    __syncthreads();

    #pragma unroll
    for (int rr = 0; rr < 4; rr++) {
        const int row = blockIdx.x * 32 + warp * 4 + rr;
        const float* wr = Wvp + (size_t)row * CK;
        float acc[BB];
        #pragma unroll
        for (int b = 0; b < BB; b++) acc[b] = 0.f;
        for (int i = lane; i < CK; i += 32) {
            const float wv = wr[i];
            #pragma unroll
            for (int b = 0; b < BB; b++) acc[b] += wv * xs[b * CK + i];
        }
        #pragma unroll
        for (int b = 0; b < BB; b++) {
            #pragma unroll
            for (int o = 16; o; o >>= 1)
                acc[b] += __shfl_xor_sync(0xffffffffu, acc[b], o);
        }
        if (lane == 0) {
            const float bv = bvp[row];
            #pragma unroll
            for (int b = 0; b < BB; b++)
                g_fused[b * (CQ + CK) + CQ + row] = acc[b] + bv;
        }
    }
}

// ============================================================
// MLP head + log_softmax
// ============================================================
__device__ __forceinline__ float warp_red(float v)
{
    #pragma unroll
    for (int o = 16; o; o >>= 1) v += __shfl_xor_sync(0xffffffffu, v, o);
    return v;
}

__global__ void head_kernel(const float* __restrict__ W1, const float* __restrict__ b1,
                            const float* __restrict__ W2, const float* __restrict__ b2,
                            float* __restrict__ out)
{
    const int b = blockIdx.x;
    __shared__ float fs[CQ + CK];
    __shared__ float hs[1024];
    __shared__ float lg[NCLS];
    __shared__ float mxs, lses;
    const int tid = threadIdx.x;
    const int warp = tid >> 5, lane = tid & 31;

    for (int i = tid; i < CQ + CK; i += 256) fs[i] = g_fused[b * (CQ + CK) + i];
    __syncthreads();

    for (int j = warp; j < 1024; j += 8) {
        const float* wr = W1 + (size_t)j * (CQ + CK);
        float s = 0.f;
        for (int i = lane; i < CQ + CK; i += 32) s += fs[i] * wr[i];
        s = warp_red(s);
        if (lane == 0) hs[j] = fmaxf(s + b1[j], 0.f);
    }
    __syncthreads();

    for (int k = warp; k < NCLS; k += 8) {
        const float* wr = W2 + (size_t)k * 1024;
        float s = 0.f;
        for (int i = lane; i < 1024; i += 32) s += hs[i] * wr[i];
        s = warp_red(s);
        if (lane == 0) lg[k] = s + b2[k];
    }
    __syncthreads();

    if (tid == 0) {
        float m = -INFINITY;
        for (int k = 0; k < NCLS; k++) m = fmaxf(m, lg[k]);
        float s = 0.f;
        for (int k = 0; k < NCLS; k++) s += expf(lg[k] - m);
        mxs = m; lses = logf(s);
    }
    __syncthreads();
    if (tid < NCLS) out[b * NCLS + tid] = lg[tid] - mxs - lses;
}

// ============================================================
extern "C" void kernel_launch(void* const* d_in, const int* in_sizes, int n_in,
                              void* d_out, int out_size)
{
    const float* img    = (const float*)d_in[0];
    const float* pc2d   = (const float*)d_in[1];
    const float* Wq     = (const float*)d_in[2];
    const float* bq     = (const float*)d_in[3];
    const float* Wk     = (const float*)d_in[4];
    const float* bk     = (const float*)d_in[5];
    const float* Wvi    = (const float*)d_in[6];
    const float* bvi    = (const float*)d_in[7];
    const float* Wvp    = (const float*)d_in[8];
    const float* bvp    = (const float*)d_in[9];
    const float* gamma1 = (const float*)d_in[10];
    const float* W1     = (const float*)d_in[11];
    const float* b1     = (const float*)d_in[12];
    const float* W2     = (const float*)d_in[13];
    const float* b2     = (const float*)d_in[14];
    float* out = (float*)d_out;

    cudaFuncSetAttribute(proj_kernel<CQ, 0>, cudaFuncAttributeMaxDynamicSharedMemorySize, PROJ_SMEM);
    cudaFuncSetAttribute(proj_kernel<CK, 1>, cudaFuncAttributeMaxDynamicSharedMemorySize, PROJ_SMEM);
    cudaFuncSetAttribute(attn_pass1, cudaFuncAttributeMaxDynamicSharedMemorySize, P1_SMEM);
    cudaFuncSetAttribute(fuse_pc_kernel, cudaFuncAttributeMaxDynamicSharedMemorySize, FP_SMEM);

    __nv_bfloat16* d_imgh = nullptr; cudaGetSymbolAddress((void**)&d_imgh, g_imgh);
    __nv_bfloat16* d_pch  = nullptr; cudaGetSymbolAddress((void**)&d_pch,  g_pch);
    __nv_bfloat16* d_wqh  = nullptr; cudaGetSymbolAddress((void**)&d_wqh,  g_wqh);
    __nv_bfloat16* d_wkh  = nullptr; cudaGetSymbolAddress((void**)&d_wkh,  g_wkh);

    dim3 blk(256);
    dim3 blk2(512);
    cvt_imgw_kernel<<<dim3(128, 5, BB), blk>>>(img, Wq, Wk);                                  // 0
    cvt_pc_half<0><<<dim3(128, 16, BB), blk>>>(pc2d);                                         // 1
    cvt_pc_half<1><<<dim3(128, 16, BB), blk>>>(pc2d);                                         // 2
    proj_kernel<CQ, 0><<<dim3(NN / 128, CQ / 128, BB), blk2, PROJ_SMEM>>>(d_wqh, d_imgh, bq); // 3 <- profiled
    proj_kernel<CK, 1><<<dim3(NN / 128, CQ / 128, BB), blk2, PROJ_SMEM>>>(d_wkh, d_pch, bk);  // 4
    attn_pass1<<<dim3(NN / 256, BB), blk2, P1_SMEM>>>();                                      // 5
    attn_pass2<<<dim3(2, 32, BB), blk>>>();                                                   // 6
    reduce_w_kernel<<<dim3(BB * NN / 256), blk>>>();                                          // 7
    reduce_xw_kernel<<<dim3(9, BB), blk>>>();                                                 // 8
    fuse_img_kernel<<<dim3(BB), blk>>>(Wvi, bvi, gamma1);                                     // 9
    fuse_pc_kernel<<<dim3(64), blk, FP_SMEM>>>(Wvp, bvp);                                     // 10
    head_kernel<<<dim3(BB), blk>>>(W1, b1, W2, b2, out);                                      // 11
}

// round 15
// speedup vs baseline: 1.2450x; 1.2450x over previous
#include <cuda_runtime.h>
#include <cuda_bf16.h>
#include <math.h>
#include <stdint.h>

#define BB 16
#define CQ 256
#define CK 2048
#define NN 4096
#define NCLS 40

// ---- scratch (static __device__ arrays; no allocation) ----
__device__ __nv_bfloat16 g_imgh[(size_t)BB * NN * CQ];
__device__ __nv_bfloat16 g_pch[(size_t)BB * NN * CK];
__device__ __nv_bfloat16 g_wqh[CQ * CQ];
__device__ __nv_bfloat16 g_wkh[CQ * CK];
__device__ __nv_bfloat16 g_qh[(size_t)BB * NN * CQ];
__device__ __nv_bfloat16 g_kh[(size_t)BB * NN * CQ];
__device__ __nv_bfloat16 g_Sh[(size_t)BB * NN * NN];   // column-permuted per 64-block
__device__ float g_rowmax[BB * NN];
__device__ float g_rowsum[BB * NN];
__device__ float g_wpart[32 * BB * NN];
__device__ float g_w[BB * NN];
__device__ float g_rp1[8 * BB * (CQ + CK)];
__device__ float g_rp2[8 * BB * CQ];
__device__ float g_ximg[BB * CQ];
__device__ float g_imgmean[BB * CQ];
__device__ float g_xpc[BB * CK];
__device__ float g_fused[BB * (CQ + CK)];

// ============================================================
// helpers
// ============================================================
__device__ __forceinline__ uint32_t smem_u32(const void* p) {
    uint32_t a;
    asm("{ .reg .u64 t; cvta.to.shared.u64 t, %1; cvt.u32.u64 %0, t; }" : "=r"(a) : "l"(p));
    return a;
}
__device__ __forceinline__ uint32_t packbf(float x, float y) {
    __nv_bfloat162 h = __floats2bfloat162_rn(x, y);
    return *reinterpret_cast<uint32_t*>(&h);
}
__device__ __forceinline__ void mma_bf16(float* c, const uint32_t* a, uint32_t b0, uint32_t b1)
{
    asm volatile(
        "mma.sync.aligned.m16n8k16.row.col.f32.bf16.bf16.f32 "
        "{%0,%1,%2,%3},{%4,%5,%6,%7},{%8,%9},{%0,%1,%2,%3};"
        : "+f"(c[0]), "+f"(c[1]), "+f"(c[2]), "+f"(c[3])
        : "r"(a[0]), "r"(a[1]), "r"(a[2]), "r"(a[3]), "r"(b0), "r"(b1));
}
__device__ __forceinline__ void ldm_x4(uint32_t* r, uint32_t addr)
{
    asm volatile("ldmatrix.sync.aligned.m8n8.x4.shared.b16 {%0,%1,%2,%3}, [%4];"
        : "=r"(r[0]), "=r"(r[1]), "=r"(r[2]), "=r"(r[3]) : "r"(addr));
}
#define CP_A16(dst, src) \
    asm volatile("cp.async.ca.shared.global [%0], [%1], 16;" :: "r"(dst), "l"(src))
#define CP_COMMIT() asm volatile("cp.async.commit_group;" ::: "memory")
#define CP_WAIT1()  asm volatile("cp.async.wait_group 1;" ::: "memory")
#define CP_WAIT0()  asm volatile("cp.async.wait_group 0;" ::: "memory")

// ============================================================
// Transpose-convert tile: 64 c-rows x 32 n-cols -> [n][c] bf16.
// ============================================================
__device__ __forceinline__ void cvt_tile64(const float* __restrict__ ib,
                                           __nv_bfloat16* __restrict__ ob, int C)
{
    __shared__ float sm[64][33];
    const int lane = threadIdx.x & 31, warp = threadIdx.x >> 5;

    #pragma unroll
    for (int i = 0; i < 8; i++) {
        int c = warp * 8 + i;
        sm[c][lane] = ib[(size_t)c * NN + lane];
    }
    __syncthreads();
    #pragma unroll
    for (int j = 0; j < 4; j++) {
        int n = warp * 4 + j;
        *reinterpret_cast<__nv_bfloat162*>(ob + (size_t)n * C + lane * 2) =
            __floats2bfloat162_rn(sm[lane * 2][n], sm[lane * 2 + 1][n]);
    }
}

__global__ __launch_bounds__(256) void cvt_imgw_kernel(const float* __restrict__ img,
                                                       const float* __restrict__ Wq,
                                                       const float* __restrict__ Wk)
{
    const int y = blockIdx.y;
    if (y < 4) {
        const int b = blockIdx.z, c0 = y * 64, n0 = blockIdx.x * 32;
        cvt_tile64(img + ((size_t)b * CQ + c0) * NN + n0,
                   g_imgh + ((size_t)b * NN + n0) * CQ + c0, CQ);
    } else {
        const int tid = threadIdx.x;
        const int total = CQ * CQ + CQ * CK;
        int i = (blockIdx.z * 128 + blockIdx.x) * 256 + tid;
        for (; i < total; i += 128 * 16 * 256) {
            if (i < CQ * CQ) g_wqh[i] = __float2bfloat16_rn(Wq[i]);
            else             g_wkh[i - CQ * CQ] = __float2bfloat16_rn(Wk[i - CQ * CQ]);
        }
    }
}

template <int HALF>
__global__ __launch_bounds__(256) void cvt_pc_half(const float* __restrict__ pc2d)
{
    const int b = blockIdx.z;
    const int c0 = (HALF * 16 + blockIdx.y) * 64;
    const int n0 = blockIdx.x * 32;
    cvt_tile64(pc2d + ((size_t)b * CK + c0) * NN + n0,
               g_pch + ((size_t)b * NN + n0) * CK + c0, CK);
}

// ============================================================
// Projection GEMM — R8-measured structure.
// ============================================================
#define PJ_PITCH 68
#define PJ_TSZ   (128 * PJ_PITCH)
#define PROJ_SMEM (4 * PJ_TSZ * 4)

template <int KDIM, int WHICH>
__global__ __launch_bounds__(512) void proj_kernel(const __nv_bfloat16* __restrict__ Wh,
                                                   const __nv_bfloat16* __restrict__ Xh,
                                                   const float* __restrict__ bias)
{
    extern __shared__ uint32_t smu[];
    const int b  = blockIdx.z;
    const int m0 = blockIdx.y * 128;
    const int n0 = blockIdx.x * 128;
    const int tid = threadIdx.x;
    const int lane = tid & 31, w = tid >> 5;
    const int wq = w & 7, wh = w >> 3;
    const int gid = lane >> 2, tig = lane & 3;
    const int NCH = KDIM / 128;
    const __nv_bfloat16* Xb = Xh + (size_t)b * NN * KDIM + (size_t)n0 * KDIM;

    const uint32_t sbase = smem_u32(smu);
    const uint32_t aoff = ((wq * 16 + (lane & 15)) * PJ_PITCH + ((lane & 16) ? 4 : 0)) * 4;
    const uint32_t boff = ((wh * 64 + (lane & 7) + ((lane & 16) >> 1)) * PJ_PITCH + ((lane & 8) ? 4 : 0)) * 4;

    float acc[8][4];
    #pragma unroll
    for (int t = 0; t < 8; t++)
        #pragma unroll
        for (int j = 0; j < 4; j++) acc[t][j] = 0.f;

    #pragma unroll
    for (int l = 0; l < 4; l++) {
        int i = tid + l * 512;
        int r = i >> 4, c = i & 15;
        CP_A16(smem_u32(smu + r * PJ_PITCH + c * 4), Wh + (size_t)(m0 + r) * KDIM + c * 8);
    }
    #pragma unroll
    for (int l = 0; l < 4; l++) {
        int i = tid + l * 512;
        int r = i >> 4, c = i & 15;
        CP_A16(smem_u32(smu + 2 * PJ_TSZ + r * PJ_PITCH + c * 4), Xb + (size_t)r * KDIM + c * 8);
    }
    CP_COMMIT();
    CP_WAIT0();
    __syncthreads();

    for (int kc = 0; kc < NCH; kc++) {
        const int cur = kc & 1, nxt = cur ^ 1;
        if (kc + 1 < NCH) {
            const int kb = (kc + 1) * 128;
            #pragma unroll
            for (int l = 0; l < 4; l++) {
                int i = tid + l * 512;
                int r = i >> 4, c = i & 15;
                CP_A16(smem_u32(smu + nxt * PJ_TSZ + r * PJ_PITCH + c * 4),
                       Wh + (size_t)(m0 + r) * KDIM + kb + c * 8);
            }
            #pragma unroll
            for (int l = 0; l < 4; l++) {
                int i = tid + l * 512;
                int r = i >> 4, c = i & 15;
                CP_A16(smem_u32(smu + (2 + nxt) * PJ_TSZ + r * PJ_PITCH + c * 4),
                       Xb + (size_t)r * KDIM + kb + c * 8);
            }
        }
        CP_COMMIT();

        const uint32_t abase = sbase + (uint32_t)(cur * PJ_TSZ) * 4 + aoff;
        const uint32_t bbase = sbase + (uint32_t)((2 + cur) * PJ_TSZ) * 4 + boff;
        #pragma unroll
        for (int ks = 0; ks < 8; ks++) {
            uint32_t a[4];
            ldm_x4(a, abase + ks * 32);
            #pragma unroll
            for (int j = 0; j < 4; j++) {
                uint32_t bf[4];
                ldm_x4(bf, bbase + (uint32_t)(j * 16 * PJ_PITCH) * 4 + ks * 32);
                mma_bf16(acc[2 * j],     a, bf[0], bf[1]);
                mma_bf16(acc[2 * j + 1], a, bf[2], bf[3]);
            }
        }
        CP_WAIT0();
        __syncthreads();
    }

    __nv_bfloat16* out = (WHICH == 0) ? g_qh : g_kh;
    const int R0 = m0 + wq * 16 + gid;
    const float bv0 = bias[R0], bv1 = bias[R0 + 8];
    #pragma unroll
    for (int t = 0; t < 8; t++) {
        int n = n0 + wh * 64 + t * 8 + tig * 2;
        __nv_bfloat16* p0 = out + ((size_t)b * NN + n) * CQ;
        __nv_bfloat16* p1 = p0 + CQ;
        p0[R0]     = __float2bfloat16_rn(acc[t][0] + bv0);
        p1[R0]     = __float2bfloat16_rn(acc[t][1] + bv0);
        p0[R0 + 8] = __float2bfloat16_rn(acc[t][2] + bv1);
        p1[R0 + 8] = __float2bfloat16_rn(acc[t][3] + bv1);
    }
}

// ============================================================
// Attention pass 1 — R11-measured (526us): fused online stats.
// ============================================================
#define P1_PITCH 132
#define P1_A (256 * P1_PITCH)
#define P1_B (128 * PJ_PITCH)
#define P1_SMEM ((P1_A + 2 * P1_B + 1024) * 4)

__global__ __launch_bounds__(512) void attn_pass1()
{
    extern __shared__ uint32_t smu[];
    float* smM = reinterpret_cast<float*>(smu + P1_A + 2 * P1_B);   // [2][256]
    float* smS = smM + 512;

    const int b  = blockIdx.y;
    const int m0 = blockIdx.x * 256;
    const int tid = threadIdx.x;
    const int lane = tid & 31, w = tid >> 5;
    const int wq = w & 7, wh = w >> 3;
    const int gid = lane >> 2, tig = lane & 3;

    const uint32_t sbase = smem_u32(smu);
    const uint32_t aoff = ((wq * 32 + (lane & 15)) * P1_PITCH + ((lane & 16) ? 4 : 0)) * 4;
    const uint32_t boff = ((wh * 64 + (lane & 7) + ((lane & 16) >> 1)) * PJ_PITCH + ((lane & 8) ? 4 : 0)) * 4;

    auto load_stage = [&](int st) {
        const int s = st >> 1, kc = st & 1;
        const __nv_bfloat16* src = g_kh + ((size_t)b * NN + s * 128) * CQ + kc * 128;
        #pragma unroll
        for (int l = 0; l < 4; l++) {
            int i = tid + l * 512;
            int r = i >> 4, c = i & 15;
            CP_A16(smem_u32(smu + P1_A + (st & 1) * P1_B + r * PJ_PITCH + c * 4),
                   src + (size_t)r * CQ + c * 8);
        }
    };

    {
        #pragma unroll
        for (int l = 0; l < 16; l++) {
            int i = tid + l * 512;
            int r = i >> 5, c = i & 31;
            CP_A16(smem_u32(smu + r * P1_PITCH + c * 4),
                   g_qh + ((size_t)b * NN + m0 + r) * CQ + c * 8);
        }
        load_stage(0);
        CP_COMMIT();
        load_stage(1);
        CP_COMMIT();
    }

    float acc[2][8][4];
    #pragma unroll
    for (int mi = 0; mi < 2; mi++)
        #pragma unroll
        for (int t = 0; t < 8; t++)
            #pragma unroll
            for (int j = 0; j < 4; j++) acc[mi][t][j] = 0.f;

    float run_m[4], run_s[4];
    #pragma unroll
    for (int k = 0; k < 4; k++) { run_m[k] = -INFINITY; run_s[k] = 0.f; }

    for (int st = 0; st < 64; st++) {
        CP_WAIT1();
        __syncthreads();

        const int kc = st & 1;
        const uint32_t bbase = sbase + (uint32_t)(P1_A + (st & 1) * P1_B) * 4;
        #pragma unroll
        for (int ks = 0; ks < 8; ks++) {
            uint32_t a0[4], a1[4];
            ldm_x4(a0, sbase + aoff + (kc * 8 + ks) * 32);
            ldm_x4(a1, sbase + aoff + 16 * P1_PITCH * 4 + (kc * 8 + ks) * 32);
            #pragma unroll
            for (int nt = 0; nt < 4; nt++) {
                uint32_t bf[4];
                ldm_x4(bf, bbase + boff + (uint32_t)(nt * 16 * PJ_PITCH) * 4 + ks * 32);
                mma_bf16(acc[0][nt * 2],     a0, bf[0], bf[1]);
                mma_bf16(acc[0][nt * 2 + 1], a0, bf[2], bf[3]);
                mma_bf16(acc[1][nt * 2],     a1, bf[0], bf[1]);
                mma_bf16(acc[1][nt * 2 + 1], a1, bf[2], bf[3]);
            }
        }
        __syncthreads();

        if (st + 2 < 64) load_stage(st + 2);
        CP_COMMIT();

        if (st & 1) {
            const int s = st >> 1;
            #pragma unroll
            for (int mi = 0; mi < 2; mi++) {
                #pragma unroll
                for (int rr = 0; rr < 2; rr++) {
                    const int k = mi * 2 + rr;
                    float vm = -INFINITY;
                    #pragma unroll
                    for (int t = 0; t < 8; t++)
                        vm = fmaxf(vm, fmaxf(acc[mi][t][rr * 2], acc[mi][t][rr * 2 + 1]));
                    vm = fmaxf(vm, __shfl_xor_sync(0xffffffffu, vm, 1));
                    vm = fmaxf(vm, __shfl_xor_sync(0xffffffffu, vm, 2));
                    const float nm = fmaxf(run_m[k], vm);
                    float ss = 0.f;
                    #pragma unroll
                    for (int t = 0; t < 8; t++)
                        ss += __expf(acc[mi][t][rr * 2] - nm) + __expf(acc[mi][t][rr * 2 + 1] - nm);
                    ss += __shfl_xor_sync(0xffffffffu, ss, 1);
                    ss += __shfl_xor_sync(0xffffffffu, ss, 2);
                    run_s[k] = run_s[k] * __expf(run_m[k] - nm) + ss;
                    run_m[k] = nm;

                    const int row = m0 + wq * 32 + mi * 16 + gid + rr * 8;
                    uint32_t pk[8];
                    #pragma unroll
                    for (int t = 0; t < 8; t++)
                        pk[t] = packbf(acc[mi][t][rr * 2], acc[mi][t][rr * 2 + 1]);
                    __nv_bfloat16* dst = g_Sh + ((size_t)b * NN + row) * NN + s * 128 + wh * 64 + tig * 16;
                    *reinterpret_cast<uint4*>(dst)     = *reinterpret_cast<uint4*>(pk);
                    *reinterpret_cast<uint4*>(dst + 8) = *reinterpret_cast<uint4*>(pk + 4);
                }
            }
            #pragma unroll
            for (int mi = 0; mi < 2; mi++)
                #pragma unroll
                for (int t = 0; t < 8; t++)
                    #pragma unroll
                    for (int j = 0; j < 4; j++) acc[mi][t][j] = 0.f;
        }
    }

    if (tig == 0) {
        #pragma unroll
        for (int k = 0; k < 4; k++) {
            const int r = wq * 32 + (k >> 1) * 16 + gid + (k & 1) * 8;
            smM[wh * 256 + r] = run_m[k];
            smS[wh * 256 + r] = run_s[k];
        }
    }
    __syncthreads();
    if (tid < 256) {
        float ma = smM[tid], mb = smM[256 + tid];
        float sa = smS[tid], sb = smS[256 + tid];
        float nm = fmaxf(ma, mb);
        g_rowmax[b * NN + m0 + tid] = nm;
        g_rowsum[b * NN + m0 + tid] = sa * __expf(ma - nm) + sb * __expf(mb - nm);
    }
}

// ============================================================
// Attention pass 2: stream bf16 S (permuted order), per-slice column sums.
// ============================================================
__global__ __launch_bounds__(256) void attn_pass2()
{
    __shared__ float rm[128], rz[128];
    const int b  = blockIdx.z;
    const int ms = blockIdx.y;
    const int nb = blockIdx.x * 2048;
    const int tid = threadIdx.x;

    if (tid < 128) {
        rm[tid] = g_rowmax[b * NN + ms * 128 + tid];
        rz[tid] = 1.0f / g_rowsum[b * NN + ms * 128 + tid];
    }
    __syncthreads();

    const __nv_bfloat16* Sp = g_Sh + ((size_t)b * NN + ms * 128) * NN + nb + tid * 8;
    float a[8];
    #pragma unroll
    for (int i = 0; i < 8; i++) a[i] = 0.f;

    for (int m = 0; m < 128; m++) {
        uint4 r = *reinterpret_cast<const uint4*>(Sp + (size_t)m * NN);
        float mx = rm[m], z = rz[m];
        __nv_bfloat162 p0 = *reinterpret_cast<__nv_bfloat162*>(&r.x);
        __nv_bfloat162 p1 = *reinterpret_cast<__nv_bfloat162*>(&r.y);
        __nv_bfloat162 p2 = *reinterpret_cast<__nv_bfloat162*>(&r.z);
        __nv_bfloat162 p3 = *reinterpret_cast<__nv_bfloat162*>(&r.w);
        a[0] += __expf(__bfloat162float(p0.x) - mx) * z;
        a[1] += __expf(__bfloat162float(p0.y) - mx) * z;
        a[2] += __expf(__bfloat162float(p1.x) - mx) * z;
        a[3] += __expf(__bfloat162float(p1.y) - mx) * z;
        a[4] += __expf(__bfloat162float(p2.x) - mx) * z;
        a[5] += __expf(__bfloat162float(p2.y) - mx) * z;
        a[6] += __expf(__bfloat162float(p3.x) - mx) * z;
        a[7] += __expf(__bfloat162float(p3.y) - mx) * z;
    }
    const float sc = 1.0f / NN;
    float* wp = g_wpart + (size_t)ms * (BB * NN) + b * NN + nb + tid * 8;
    *reinterpret_cast<float4*>(wp)     = make_float4(a[0] * sc, a[1] * sc, a[2] * sc, a[3] * sc);
    *reinterpret_cast<float4*>(wp + 4) = make_float4(a[4] * sc, a[5] * sc, a[6] * sc, a[7] * sc);
}

// reduce + inverse column permutation
__global__ void reduce_w_kernel()
{
    const int flat = blockIdx.x * 256 + threadIdx.x;
    const int a = flat & 63;
    const int sa = ((a & 7) >> 1) * 16 + ((a >> 3) & 7) * 2 + (a & 1);
    const int src = (flat & ~63) | sa;
    float s = 0.f;
    #pragma unroll
    for (int ms = 0; ms < 32; ms++) s += g_wpart[ms * (BB * NN) + src];
    g_w[flat] = s;
}

// ============================================================
// Weighted/plain reductions from bf16 [n][c] copies — PARALLEL version.
// grid (9 chunks, 8 n-slices, BB), block 256.
// cg = tid&63 owns 4 channels (uint2); ng = tid>>6; slice = 512 n.
// Partials to g_rp1/g_rp2, merged by reduce_xw_merge.
// ============================================================
__global__ __launch_bounds__(256) void reduce_xw_kernel()
{
    __shared__ float ws[512];
    __shared__ float red1[4][256];
    __shared__ float red2[4][256];
    const int b = blockIdx.z;
    const int ns = blockIdx.y;
    const int chunk = blockIdx.x;
    const int tid = threadIdx.x;
    const int cg = tid & 63, ng = tid >> 6;

    for (int i = tid; i < 512; i += 256) ws[i] = g_w[b * NN + ns * 512 + i];
    __syncthreads();

    const bool isimg = (chunk == 0);
    const int C = isimg ? CQ : CK;
    const int c0 = isimg ? 0 : (chunk - 1) * 256;
    const __nv_bfloat16* X = (isimg ? g_imgh + (size_t)b * NN * CQ
                                    : g_pch + (size_t)b * NN * CK)
                             + (size_t)(ns * 512) * C + c0 + cg * 4;

    float s1[4] = {0.f, 0.f, 0.f, 0.f};
    float s2[4] = {0.f, 0.f, 0.f, 0.f};
    #pragma unroll 4
    for (int i = 0; i < 128; i++) {
        const int n = ng + i * 4;
        uint2 v = *reinterpret_cast<const uint2*>(X + (size_t)n * C);
        __nv_bfloat162 p0 = *reinterpret_cast<__nv_bfloat162*>(&v.x);
        __nv_bfloat162 p1 = *reinterpret_cast<__nv_bfloat162*>(&v.y);
        const float wv = ws[n];
        float x0 = __bfloat162float(p0.x), x1 = __bfloat162float(p0.y);
        float x2 = __bfloat162float(p1.x), x3 = __bfloat162float(p1.y);
        s1[0] += wv * x0; s1[1] += wv * x1; s1[2] += wv * x2; s1[3] += wv * x3;
        s2[0] += x0; s2[1] += x1; s2[2] += x2; s2[3] += x3;
    }
    #pragma unroll
    for (int j = 0; j < 4; j++) {
        red1[ng][cg * 4 + j] = s1[j];
        red2[ng][cg * 4 + j] = s2[j];
    }
    __syncthreads();
    const int ch = tid;
    float a = red1[0][ch] + red1[1][ch] + red1[2][ch] + red1[3][ch];
    g_rp1[(ns * BB + b) * (CQ + CK) + (isimg ? ch : CQ + c0 + ch)] = a;
    if (isimg) {
        float m = red2[0][ch] + red2[1][ch] + red2[2][ch] + red2[3][ch];
        g_rp2[(ns * BB + b) * CQ + ch] = m;
    }
}

__global__ void reduce_xw_merge()
{
    const int f = blockIdx.x * 256 + threadIdx.x;   // over BB*(CQ+CK)
    const int b = f / (CQ + CK), c = f % (CQ + CK);
    float s = 0.f;
    #pragma unroll
    for (int ns = 0; ns < 8; ns++) s += g_rp1[(ns * BB + b) * (CQ + CK) + c];
    if (c < CQ) {
        float m = 0.f;
        #pragma unroll
        for (int ns = 0; ns < 8; ns++) m += g_rp2[(ns * BB + b) * CQ + c];
        g_ximg[b * CQ + c] = s;
        g_imgmean[b * CQ + c] = m * (1.0f / NN);
    } else {
        g_xpc[b * CK + (c - CQ)] = s;
    }
}

// ============================================================
// Fused vector — img part
// ============================================================
__global__ void fuse_img_kernel(const float* __restrict__ Wvi, const float* __restrict__ bvi,
                                const float* __restrict__ gamma1)
{
    const int b = blockIdx.x;
    const int t = threadIdx.x;
    __shared__ float xs[CQ];
    if (t < CQ) xs[t] = g_ximg[b * CQ + t];
    __syncthreads();
    float acc = 0.f;
    const float* wr = Wvi + (size_t)t * CQ;
    for (int i = 0; i < CQ; i++) acc += wr[i] * xs[i];
    float g = gamma1[0];
    g_fused[b * (CQ + CK) + t] = g * (acc + bvi[t]) + g_imgmean[b * CQ + t];
}

// ============================================================
// Fused vector — pc part (batched coalesced GEMV)
// ============================================================
#define FP_SMEM (BB * CK * 4)

__global__ __launch_bounds__(256) void fuse_pc_kernel(const float* __restrict__ Wvp,
                                                      const float* __restrict__ bvp)
{
    extern __shared__ float xs[];
    const int tid = threadIdx.x;
    const int warp = tid >> 5, lane = tid & 31;

    for (int i = tid; i < BB * CK; i += 256) xs[i] = g_xpc[i];
    __syncthreads();

    #pragma unroll
    for (int rr = 0; rr < 4; rr++) {
        const int row = blockIdx.x * 32 + warp * 4 + rr;
        const float* wr = Wvp + (size_t)row * CK;
        float acc[BB];
        #pragma unroll
        for (int b = 0; b < BB; b++) acc[b] = 0.f;
        for (int i = lane; i < CK; i += 32) {
            const float wv = wr[i];
            #pragma unroll
            for (int b = 0; b < BB; b++) acc[b] += wv * xs[b * CK + i];
        }
        #pragma unroll
        for (int b = 0; b < BB; b++) {
            #pragma unroll
            for (int o = 16; o; o >>= 1)
                acc[b] += __shfl_xor_sync(0xffffffffu, acc[b], o);
        }
        if (lane == 0) {
            const float bv = bvp[row];
            #pragma unroll
            for (int b = 0; b < BB; b++)
                g_fused[b * (CQ + CK) + CQ + row] = acc[b] + bv;
        }
    }
}

// ============================================================
// MLP head + log_softmax
// ============================================================
__device__ __forceinline__ float warp_red(float v)
{
    #pragma unroll
    for (int o = 16; o; o >>= 1) v += __shfl_xor_sync(0xffffffffu, v, o);
    return v;
}

__global__ void head_kernel(const float* __restrict__ W1, const float* __restrict__ b1,
                            const float* __restrict__ W2, const float* __restrict__ b2,
                            float* __restrict__ out)
{
    const int b = blockIdx.x;
    __shared__ float fs[CQ + CK];
    __shared__ float hs[1024];
    __shared__ float lg[NCLS];
    __shared__ float mxs, lses;
    const int tid = threadIdx.x;
    const int warp = tid >> 5, lane = tid & 31;

    for (int i = tid; i < CQ + CK; i += 256) fs[i] = g_fused[b * (CQ + CK) + i];
    __syncthreads();

    for (int j = warp; j < 1024; j += 8) {
        const float* wr = W1 + (size_t)j * (CQ + CK);
        float s = 0.f;
        for (int i = lane; i < CQ + CK; i += 32) s += fs[i] * wr[i];
        s = warp_red(s);
        if (lane == 0) hs[j] = fmaxf(s + b1[j], 0.f);
    }
    __syncthreads();

    for (int k = warp; k < NCLS; k += 8) {
        const float* wr = W2 + (size_t)k * 1024;
        float s = 0.f;
        for (int i = lane; i < 1024; i += 32) s += hs[i] * wr[i];
        s = warp_red(s);
        if (lane == 0) lg[k] = s + b2[k];
    }
    __syncthreads();

    if (tid == 0) {
        float m = -INFINITY;
        for (int k = 0; k < NCLS; k++) m = fmaxf(m, lg[k]);
        float s = 0.f;
        for (int k = 0; k < NCLS; k++) s += expf(lg[k] - m);
        mxs = m; lses = logf(s);
    }
    __syncthreads();
    if (tid < NCLS) out[b * NCLS + tid] = lg[tid] - mxs - lses;
}

// ============================================================
extern "C" void kernel_launch(void* const* d_in, const int* in_sizes, int n_in,
                              void* d_out, int out_size)
{
    const float* img    = (const float*)d_in[0];
    const float* pc2d   = (const float*)d_in[1];
    const float* Wq     = (const float*)d_in[2];
    const float* bq     = (const float*)d_in[3];
    const float* Wk     = (const float*)d_in[4];
    const float* bk     = (const float*)d_in[5];
    const float* Wvi    = (const float*)d_in[6];
    const float* bvi    = (const float*)d_in[7];
    const float* Wvp    = (const float*)d_in[8];
    const float* bvp    = (const float*)d_in[9];
    const float* gamma1 = (const float*)d_in[10];
    const float* W1     = (const float*)d_in[11];
    const float* b1     = (const float*)d_in[12];
    const float* W2     = (const float*)d_in[13];
    const float* b2     = (const float*)d_in[14];
    float* out = (float*)d_out;

    cudaFuncSetAttribute(proj_kernel<CQ, 0>, cudaFuncAttributeMaxDynamicSharedMemorySize, PROJ_SMEM);
    cudaFuncSetAttribute(proj_kernel<CK, 1>, cudaFuncAttributeMaxDynamicSharedMemorySize, PROJ_SMEM);
    cudaFuncSetAttribute(attn_pass1, cudaFuncAttributeMaxDynamicSharedMemorySize, P1_SMEM);
    cudaFuncSetAttribute(fuse_pc_kernel, cudaFuncAttributeMaxDynamicSharedMemorySize, FP_SMEM);

    __nv_bfloat16* d_imgh = nullptr; cudaGetSymbolAddress((void**)&d_imgh, g_imgh);
    __nv_bfloat16* d_pch  = nullptr; cudaGetSymbolAddress((void**)&d_pch,  g_pch);
    __nv_bfloat16* d_wqh  = nullptr; cudaGetSymbolAddress((void**)&d_wqh,  g_wqh);
    __nv_bfloat16* d_wkh  = nullptr; cudaGetSymbolAddress((void**)&d_wkh,  g_wkh);

    dim3 blk(256);
    dim3 blk2(512);
    cvt_imgw_kernel<<<dim3(128, 5, BB), blk>>>(img, Wq, Wk);                                  // 0
    cvt_pc_half<0><<<dim3(128, 16, BB), blk>>>(pc2d);                                         // 1
    cvt_pc_half<1><<<dim3(128, 16, BB), blk>>>(pc2d);                                         // 2
    attn_pass1_dummy:
    proj_kernel<CQ, 0><<<dim3(NN / 128, CQ / 128, BB), blk2, PROJ_SMEM>>>(d_wqh, d_imgh, bq); // 3
    proj_kernel<CK, 1><<<dim3(NN / 128, CQ / 128, BB), blk2, PROJ_SMEM>>>(d_wkh, d_pch, bk);  // 4
    attn_pass1<<<dim3(NN / 256, BB), blk2, P1_SMEM>>>();                                      // 5
    attn_pass2<<<dim3(2, 32, BB), blk>>>();                                                   // 6
    reduce_w_kernel<<<dim3(BB * NN / 256), blk>>>();                                          // 7
    reduce_xw_kernel<<<dim3(9, 8, BB), blk>>>();                                              // 8
    reduce_xw_merge<<<dim3(BB * (CQ + CK) / 256), blk>>>();                                   // 9
    fuse_img_kernel<<<dim3(BB), blk>>>(Wvi, bvi, gamma1);                                     // 10
    fuse_pc_kernel<<<dim3(64), blk, FP_SMEM>>>(Wvp, bvp);                                     // 11
    head_kernel<<<dim3(BB), blk>>>(W1, b1, W2, b2, out);                                      // 12
}